// round 16
// baseline (speedup 1.0000x reference)
#include <cuda_runtime.h>
#include <cuda_fp16.h>
#include <math.h>
#include <stdint.h>

#define NN    10000
#define EE    320000
#define FIN   7
#define DD    256
#define HH    8
#define CC    32
#define LL    2
#define GG    16
#define SLOPE 0.2f

#define CSR_BLOCKS 296            // 2 CTAs/SM on 148 SMs: always co-resident

// ---------------- scratch (static __device__, no allocation) ----------------
__device__ float g_h  [NN * DD];
__device__ float g_xr [NN * DD];
__device__ __align__(16) __half g_xlh[NN * DD];             // fp16 xl (gathered)
__device__ __align__(16) __half g_hh[NN * DD];              // fp16 h (GEMM A)
__device__ __align__(16) __half g_wh[LL * 2 * DD * DD];     // [layer][sel][j][k] = W[k][j]
__device__ int   g_deg   [NN];
__device__ int   g_rowptr[NN + 1];
__device__ int   g_cursor[NN];
__device__ int   g_csrc  [EE];
__device__ int   g_bsum  [40];
__device__ float g_pool  [GG * DD];
__device__ float g_cnt   [GG];
__device__ int   g_bar_cnt = 0;
__device__ int   g_bar_gen = 0;

// ---------------- grid barrier (persistent kernel, replay-safe) -------------
__device__ __forceinline__ void grid_barrier() {
    __syncthreads();
    if (threadIdx.x == 0) {
        int my_gen = atomicAdd(&g_bar_gen, 0);
        __threadfence();
        int r = atomicAdd(&g_bar_cnt, 1);
        if (r == CSR_BLOCKS - 1) {
            atomicExch(&g_bar_cnt, 0);      // reset BEFORE release
            __threadfence();
            atomicAdd(&g_bar_gen, 1);
        } else {
            while (atomicAdd(&g_bar_gen, 0) == my_gen) {}
        }
    }
    __syncthreads();
}

// ---------------- fused CSR build: zero + hist + scan + scatter -------------
__global__ __launch_bounds__(256) void csr_kernel(const int* __restrict__ ei) {
    __shared__ int s[256];
    const int b   = blockIdx.x;
    const int t   = threadIdx.x;
    const int gt  = b * 256 + t;
    const int GT  = CSR_BLOCKS * 256;

    // phase 0: zero deg / pool / cnt
    for (int i = gt; i < NN; i += GT)      g_deg[i] = 0;
    for (int i = gt; i < GG * DD; i += GT) g_pool[i] = 0.f;
    if (gt < GG) g_cnt[gt] = 0.f;
    grid_barrier();

    // phase 1: histogram of dst
    for (int e = gt; e < EE; e += GT)
        atomicAdd(&g_deg[ei[EE + e]], 1);
    grid_barrier();

    // phase 2: 40 blocks do 256-wide local exclusive scans
    if (b < 40) {
        int i = b * 256 + t;
        int v = (i < NN) ? g_deg[i] : 0;
        s[t] = v;
        __syncthreads();
#pragma unroll
        for (int off = 1; off < 256; off <<= 1) {
            int u = (t >= off) ? s[t - off] : 0;
            __syncthreads();
            s[t] += u;
            __syncthreads();
        }
        if (i < NN) g_rowptr[i] = s[t] - v;
        if (t == 255) g_bsum[b] = s[255];
    }
    grid_barrier();

    // phase 3: serial prefix over 40 block sums
    if (b == 0 && t == 0) {
        int r = 0;
#pragma unroll
        for (int j = 0; j < 40; ++j) { int v = g_bsum[j]; g_bsum[j] = r; r += v; }
        g_rowptr[NN] = r;
    }
    grid_barrier();

    // phase 4: apply block offsets, init cursor
    for (int i = gt; i < NN; i += GT) {
        int v = g_rowptr[i] + g_bsum[i >> 8];
        g_rowptr[i] = v;
        g_cursor[i] = v;
    }
    grid_barrier();

    // phase 5: scatter src by dst
    for (int e = gt; e < EE; e += GT) {
        int d   = ei[EE + e];
        int pos = atomicAdd(&g_cursor[d], 1);
        g_csrc[pos] = ei[e];
    }
}

// ---------------- fused prep: proj (blocks 0..NN-1) + conv_w (rest) --------
__global__ __launch_bounds__(256) void prep_kernel(const float* __restrict__ x,
                                                   const float* __restrict__ Wp,
                                                   const float* __restrict__ bp,
                                                   const float* __restrict__ Wlm,
                                                   const float* __restrict__ Wrm) {
    const int blk = blockIdx.x;
    const int tidx = threadIdx.x;
    if (blk < NN) {
        int n = blk, d = tidx;
        float acc = bp[d];
#pragma unroll
        for (int f = 0; f < FIN; ++f)
            acc += x[n * FIN + f] * Wp[f * DD + d];
        size_t o = (size_t)n * DD + d;
        g_h[o]  = acc;
        g_hh[o] = __float2half(acc);
    } else {
        int idx = blk - NN;              // 0 .. 2*2*DD-1
        int j   = idx & (DD - 1);
        int sel = (idx >> 8) & 1;
        int l   = idx >> 9;
        const float* W = (sel ? Wrm : Wlm) + (size_t)l * DD * DD;
        g_wh[(((size_t)l * 2 + sel) * DD + j) * DD + tidx] =
            __float2half(W[tidx * DD + j]);
    }
}

// ---------------- tensor-core GEMM (fp16, 4-stage cp.async, 64x128 blocks) --
__device__ __forceinline__ void mma16816(float* c, const uint32_t* a, const uint32_t* b) {
    asm volatile(
        "mma.sync.aligned.m16n8k16.row.col.f32.f16.f16.f32 "
        "{%0,%1,%2,%3}, {%4,%5,%6,%7}, {%8,%9}, {%0,%1,%2,%3};"
        : "+f"(c[0]), "+f"(c[1]), "+f"(c[2]), "+f"(c[3])
        : "r"(a[0]), "r"(a[1]), "r"(a[2]), "r"(a[3]), "r"(b[0]), "r"(b[1]));
}

__device__ __forceinline__ void cp16(uint32_t dst, const void* src, int srcsz) {
    asm volatile("cp.async.cg.shared.global [%0], [%1], 16, %2;"
                 :: "r"(dst), "l"(src), "r"(srcsz));
}
#define CP_COMMIT() asm volatile("cp.async.commit_group;" ::: "memory")
#define CP_WAIT(n)  asm volatile("cp.async.wait_group %0;" :: "n"(n) : "memory")

__global__ __launch_bounds__(128) void mma_gemm_kernel(int layer) {
    __shared__ __align__(16) __half sA[4][64][16];
    __shared__ __align__(16) __half sB[4][128][16];

    const int tid  = threadIdx.x;
    const int wid  = tid >> 5;
    const int lane = tid & 31;
    const int wm   = wid & 1;
    const int wn   = wid >> 1;
    const int rg   = lane >> 2;
    const int tg   = lane & 3;

    const int mbase   = blockIdx.x * 64;
    const int nhalf   = blockIdx.y & 1;
    const int sel     = blockIdx.y >> 1;
    const int colBase = nhalf * 128;
    const __half* W = g_wh + ((size_t)layer * 2 + sel) * DD * DD;

    const int srow = tid >> 1;
    const int soff = (tid & 1) * 8;
    const int grA  = mbase + srow;
    const size_t gA  = (size_t)grA * DD + soff;
    const size_t gB0 = (size_t)(colBase + srow) * DD + soff;
    const size_t gB1 = (size_t)(colBase + srow + 64) * DD + soff;
    const int predA = (grA < NN) ? 16 : 0;
    const uint32_t uA  = (uint32_t)__cvta_generic_to_shared(&sA[0][0][0])
                       + (uint32_t)(srow * 32 + soff * 2);
    const uint32_t uB0 = (uint32_t)__cvta_generic_to_shared(&sB[0][0][0])
                       + (uint32_t)(srow * 32 + soff * 2);
    const uint32_t uB1 = uB0 + 64u * 32u;

    float acc[2][8][4];
#pragma unroll
    for (int mt = 0; mt < 2; ++mt)
#pragma unroll
        for (int nt = 0; nt < 8; ++nt)
#pragma unroll
            for (int q = 0; q < 4; ++q) acc[mt][nt][q] = 0.f;

#define LOAD_STAGE(kt, buf) do {                                \
        uint32_t boA = (uint32_t)(buf) * 2048u;                 \
        uint32_t boB = (uint32_t)(buf) * 4096u;                 \
        cp16(uA  + boA, g_hh + gA  + (kt) * 16, predA);         \
        cp16(uB0 + boB, W    + gB0 + (kt) * 16, 16);            \
        cp16(uB1 + boB, W    + gB1 + (kt) * 16, 16);            \
    } while (0)

    LOAD_STAGE(0, 0); CP_COMMIT();
    LOAD_STAGE(1, 1); CP_COMMIT();
    LOAD_STAGE(2, 2); CP_COMMIT();

    for (int kt = 0; kt < 16; ++kt) {
        const int buf = kt & 3;
        CP_WAIT(2);
        __syncthreads();
        if (kt + 3 < 16) LOAD_STAGE(kt + 3, (kt + 3) & 3);
        CP_COMMIT();

        uint32_t a[2][4];
#pragma unroll
        for (int mt = 0; mt < 2; ++mt) {
            int r = wm * 32 + mt * 16;
            a[mt][0] = *(const uint32_t*)&sA[buf][r + rg    ][tg * 2    ];
            a[mt][1] = *(const uint32_t*)&sA[buf][r + rg + 8][tg * 2    ];
            a[mt][2] = *(const uint32_t*)&sA[buf][r + rg    ][tg * 2 + 8];
            a[mt][3] = *(const uint32_t*)&sA[buf][r + rg + 8][tg * 2 + 8];
        }
        uint32_t b[8][2];
#pragma unroll
        for (int nt = 0; nt < 8; ++nt) {
            int n = wn * 64 + nt * 8 + rg;
            b[nt][0] = *(const uint32_t*)&sB[buf][n][tg * 2    ];
            b[nt][1] = *(const uint32_t*)&sB[buf][n][tg * 2 + 8];
        }
#pragma unroll
        for (int mt = 0; mt < 2; ++mt)
#pragma unroll
            for (int nt = 0; nt < 8; ++nt)
                mma16816(acc[mt][nt], a[mt], b[nt]);
    }
#undef LOAD_STAGE

#pragma unroll
    for (int mt = 0; mt < 2; ++mt) {
#pragma unroll
        for (int nt = 0; nt < 8; ++nt) {
            int row0 = mbase + wm * 32 + mt * 16 + rg;
            int col  = colBase + wn * 64 + nt * 8 + tg * 2;
            if (sel == 0) {
                if (row0 < NN)
                    *(__half2*)&g_xlh[(size_t)row0 * DD + col] =
                        __floats2half2_rn(acc[mt][nt][0], acc[mt][nt][1]);
                if (row0 + 8 < NN)
                    *(__half2*)&g_xlh[(size_t)(row0 + 8) * DD + col] =
                        __floats2half2_rn(acc[mt][nt][2], acc[mt][nt][3]);
            } else {
                if (row0 < NN)
                    *(float2*)&g_xr[(size_t)row0 * DD + col] =
                        make_float2(acc[mt][nt][0], acc[mt][nt][1]);
                if (row0 + 8 < NN)
                    *(float2*)&g_xr[(size_t)(row0 + 8) * DD + col] =
                        make_float2(acc[mt][nt][2], acc[mt][nt][3]);
            }
        }
    }
}

// ---------------- GATv2 edge softmax + aggregate (fp16 gather, 4x unroll) ---
__device__ __forceinline__ float gat_logit2(const float2 a01, const float2 a23,
                                            const float4 xr4, const float4 att4) {
    float vx = a01.x + xr4.x, vy = a01.y + xr4.y;
    float vz = a23.x + xr4.z, vw = a23.y + xr4.w;
    return fmaxf(vx, SLOPE * vx) * att4.x
         + fmaxf(vy, SLOPE * vy) * att4.y
         + fmaxf(vz, SLOPE * vz) * att4.z
         + fmaxf(vw, SLOPE * vw) * att4.w;
}

__global__ __launch_bounds__(256) void gat_kernel(const float* __restrict__ att_l,
                                                  const float* __restrict__ bconv_l) {
    const int w    = threadIdx.x >> 5;
    const int lane = threadIdx.x & 31;
    const int n    = blockIdx.x * 4 + (w >> 1);
    const int half = w & 1;
    const int d    = half * 128 + lane * 4;

    const int r0 = g_rowptr[n];
    const int r1 = g_rowptr[n + 1];

    const float4 xr4  = *(const float4*)&g_xr[(size_t)n * DD + d];
    const float4 att4 = *(const float4*)&att_l[d];

    float4 acc = make_float4(0.f, 0.f, 0.f, 0.f);
    float ssum = 0.f;

    int k = r0;
    for (; k + 3 < r1; k += 4) {
        int s0 = g_csrc[k];
        int s1 = g_csrc[k + 1];
        int s2 = g_csrc[k + 2];
        int s3 = g_csrc[k + 3];
        uint2 ua = *(const uint2*)&g_xlh[(size_t)s0 * DD + d];
        uint2 ub = *(const uint2*)&g_xlh[(size_t)s1 * DD + d];
        uint2 uc = *(const uint2*)&g_xlh[(size_t)s2 * DD + d];
        uint2 ud = *(const uint2*)&g_xlh[(size_t)s3 * DD + d];
        float2 a01 = __half22float2(*(__half2*)&ua.x);
        float2 a23 = __half22float2(*(__half2*)&ua.y);
        float2 b01 = __half22float2(*(__half2*)&ub.x);
        float2 b23 = __half22float2(*(__half2*)&ub.y);
        float2 c01 = __half22float2(*(__half2*)&uc.x);
        float2 c23 = __half22float2(*(__half2*)&uc.y);
        float2 d01 = __half22float2(*(__half2*)&ud.x);
        float2 d23 = __half22float2(*(__half2*)&ud.y);

        float pa = gat_logit2(a01, a23, xr4, att4);
        float pb = gat_logit2(b01, b23, xr4, att4);
        float pc = gat_logit2(c01, c23, xr4, att4);
        float pd = gat_logit2(d01, d23, xr4, att4);

        pa += __shfl_xor_sync(0xffffffffu, pa, 1);
        pb += __shfl_xor_sync(0xffffffffu, pb, 1);
        pc += __shfl_xor_sync(0xffffffffu, pc, 1);
        pd += __shfl_xor_sync(0xffffffffu, pd, 1);
        pa += __shfl_xor_sync(0xffffffffu, pa, 2);
        pb += __shfl_xor_sync(0xffffffffu, pb, 2);
        pc += __shfl_xor_sync(0xffffffffu, pc, 2);
        pd += __shfl_xor_sync(0xffffffffu, pd, 2);
        pa += __shfl_xor_sync(0xffffffffu, pa, 4);
        pb += __shfl_xor_sync(0xffffffffu, pb, 4);
        pc += __shfl_xor_sync(0xffffffffu, pc, 4);
        pd += __shfl_xor_sync(0xffffffffu, pd, 4);

        float wa = __expf(pa), wb = __expf(pb);
        float wc = __expf(pc), wd = __expf(pd);
        acc.x += wa * a01.x + wb * b01.x + wc * c01.x + wd * d01.x;
        acc.y += wa * a01.y + wb * b01.y + wc * c01.y + wd * d01.y;
        acc.z += wa * a23.x + wb * b23.x + wc * c23.x + wd * d23.x;
        acc.w += wa * a23.y + wb * b23.y + wc * c23.y + wd * d23.y;
        ssum  += (wa + wb) + (wc + wd);
    }
    for (; k < r1; ++k) {
        int s0 = g_csrc[k];
        uint2 ua = *(const uint2*)&g_xlh[(size_t)s0 * DD + d];
        float2 a01 = __half22float2(*(__half2*)&ua.x);
        float2 a23 = __half22float2(*(__half2*)&ua.y);
        float pa = gat_logit2(a01, a23, xr4, att4);
        pa += __shfl_xor_sync(0xffffffffu, pa, 1);
        pa += __shfl_xor_sync(0xffffffffu, pa, 2);
        pa += __shfl_xor_sync(0xffffffffu, pa, 4);
        float wa = __expf(pa);
        acc.x += wa * a01.x; acc.y += wa * a01.y;
        acc.z += wa * a23.x; acc.w += wa * a23.y;
        ssum  += wa;
    }

    const float inv = (r1 > r0) ? (1.f / ssum) : 0.f;
    const float4 bc4 = *(const float4*)&bconv_l[d];
    const size_t o = (size_t)n * DD + d;
    float4 hv = *(float4*)&g_h[o];
    hv.x += acc.x * inv + bc4.x;
    hv.y += acc.y * inv + bc4.y;
    hv.z += acc.z * inv + bc4.z;
    hv.w += acc.w * inv + bc4.w;
    *(float4*)&g_h[o] = hv;

    __half2 h01 = __floats2half2_rn(hv.x, hv.y);
    __half2 h23 = __floats2half2_rn(hv.z, hv.w);
    *(__half2*)&g_hh[o]     = h01;
    *(__half2*)&g_hh[o + 2] = h23;
}

// ---------------- global mean pool + counts (run-compressed atomics) --------
__global__ void pool_kernel(const int* __restrict__ batch) {
    const int d = threadIdx.x;
    const int per = (NN + gridDim.x - 1) / gridDim.x;
    int n0 = blockIdx.x * per;
    int n1 = n0 + per; if (n1 > NN) n1 = NN;
    if (n0 >= n1) return;
    int cur = batch[n0];
    float accv = 0.f;
    int   cc   = 0;
    for (int n = n0; n < n1; ++n) {
        int b = batch[n];
        if (b != cur) {
            atomicAdd(&g_pool[cur * DD + d], accv);
            if (d == 0) atomicAdd(&g_cnt[cur], (float)cc);
            accv = 0.f; cc = 0;
            cur = b;
        }
        accv += g_h[(size_t)n * DD + d];
        cc   += 1;
    }
    atomicAdd(&g_pool[cur * DD + d], accv);
    if (d == 0) atomicAdd(&g_cnt[cur], (float)cc);
}

// ---------------- prediction head ----------------
__global__ void pred_kernel(const float* __restrict__ Wpred,
                            const float* __restrict__ bpred,
                            float* __restrict__ out) {
    const int g    = threadIdx.x >> 5;
    const int lane = threadIdx.x & 31;
    float s = 0.f;
    for (int d = lane; d < DD; d += 32)
        s += g_pool[g * DD + d] * Wpred[d];
#pragma unroll
    for (int off = 16; off; off >>= 1)
        s += __shfl_xor_sync(0xffffffffu, s, off);
    if (lane == 0)
        out[g] = s / fmaxf(g_cnt[g], 1.0f) + bpred[0];
}

// ---------------- launch (8 kernels; slot 4 = gat_kernel, profiled) ---------
extern "C" void kernel_launch(void* const* d_in, const int* in_sizes, int n_in,
                              void* d_out, int out_size) {
    const float* x     = (const float*)d_in[0];
    const int*   ei    = (const int*)  d_in[1];
    const int*   batch = (const int*)  d_in[2];
    const float* Wp    = (const float*)d_in[3];
    const float* bp    = (const float*)d_in[4];
    const float* Wl    = (const float*)d_in[5];
    const float* Wr    = (const float*)d_in[6];
    const float* att   = (const float*)d_in[7];
    const float* bconv = (const float*)d_in[8];
    const float* Wpred = (const float*)d_in[9];
    const float* bpred = (const float*)d_in[10];
    float* out = (float*)d_out;

    dim3 ggrid((NN + 63) / 64, 4);

    csr_kernel<<<CSR_BLOCKS, 256>>>(ei);                       // 1
    prep_kernel<<<NN + 2 * 2 * DD, 256>>>(x, Wp, bp, Wl, Wr);  // 2
    mma_gemm_kernel<<<ggrid, 128>>>(0);                        // 3
    gat_kernel<<<NN / 4, 256>>>(att, bconv);                   // 4 (profiled)
    mma_gemm_kernel<<<ggrid, 128>>>(1);                        // 5
    gat_kernel<<<NN / 4, 256>>>(att + HH * CC, bconv + DD);    // 6
    pool_kernel<<<64, DD>>>(batch);                            // 7
    pred_kernel<<<1, GG * 32>>>(Wpred, bpred, out);            // 8
}

// round 17
// speedup vs baseline: 1.0190x; 1.0190x over previous
#include <cuda_runtime.h>
#include <cuda_fp16.h>
#include <math.h>
#include <stdint.h>

#define NN    10000
#define EE    320000
#define FIN   7
#define DD    256
#define HH    8
#define CC    32
#define LL    2
#define GG    16
#define SLOPE 0.2f

#define CSR_BLOCKS 296            // 2 CTAs/SM on 148 SMs: always co-resident

// ---------------- scratch (static __device__, no allocation) ----------------
__device__ float g_h  [NN * DD];
__device__ float g_xr [NN * DD];
__device__ __align__(16) __half g_xlh[NN * DD];             // fp16 xl (gathered)
__device__ __align__(16) __half g_hh[NN * DD];              // fp16 h (GEMM A)
__device__ __align__(16) __half g_wh[LL * 2 * DD * DD];     // [layer][sel][j][k] = W[k][j]
__device__ int   g_deg   [NN];
__device__ int   g_rowptr[NN + 1];
__device__ int   g_cursor[NN];
__device__ int   g_csrc  [EE];                              // pre-scaled: src*DD
__device__ int   g_bsum  [40];
__device__ float g_pool  [GG * DD];
__device__ float g_cnt   [GG];
__device__ int   g_bar_cnt = 0;
__device__ int   g_bar_gen = 0;

// ---------------- grid barrier (persistent kernel, replay-safe) -------------
__device__ __forceinline__ void grid_barrier() {
    __syncthreads();
    if (threadIdx.x == 0) {
        int my_gen = atomicAdd(&g_bar_gen, 0);
        __threadfence();
        int r = atomicAdd(&g_bar_cnt, 1);
        if (r == CSR_BLOCKS - 1) {
            atomicExch(&g_bar_cnt, 0);      // reset BEFORE release
            __threadfence();
            atomicAdd(&g_bar_gen, 1);
        } else {
            while (atomicAdd(&g_bar_gen, 0) == my_gen) {}
        }
    }
    __syncthreads();
}

// ---------------- fused CSR build: zero + hist + scan + scatter -------------
__global__ __launch_bounds__(256) void csr_kernel(const int* __restrict__ ei) {
    __shared__ int s[256];
    const int b   = blockIdx.x;
    const int t   = threadIdx.x;
    const int gt  = b * 256 + t;
    const int GT  = CSR_BLOCKS * 256;

    for (int i = gt; i < NN; i += GT)      g_deg[i] = 0;
    for (int i = gt; i < GG * DD; i += GT) g_pool[i] = 0.f;
    if (gt < GG) g_cnt[gt] = 0.f;
    grid_barrier();

    for (int e = gt; e < EE; e += GT)
        atomicAdd(&g_deg[ei[EE + e]], 1);
    grid_barrier();

    if (b < 40) {
        int i = b * 256 + t;
        int v = (i < NN) ? g_deg[i] : 0;
        s[t] = v;
        __syncthreads();
#pragma unroll
        for (int off = 1; off < 256; off <<= 1) {
            int u = (t >= off) ? s[t - off] : 0;
            __syncthreads();
            s[t] += u;
            __syncthreads();
        }
        if (i < NN) g_rowptr[i] = s[t] - v;
        if (t == 255) g_bsum[b] = s[255];
    }
    grid_barrier();

    if (b == 0 && t == 0) {
        int r = 0;
#pragma unroll
        for (int j = 0; j < 40; ++j) { int v = g_bsum[j]; g_bsum[j] = r; r += v; }
        g_rowptr[NN] = r;
    }
    grid_barrier();

    for (int i = gt; i < NN; i += GT) {
        int v = g_rowptr[i] + g_bsum[i >> 8];
        g_rowptr[i] = v;
        g_cursor[i] = v;
    }
    grid_barrier();

    for (int e = gt; e < EE; e += GT) {
        int d   = ei[EE + e];
        int pos = atomicAdd(&g_cursor[d], 1);
        g_csrc[pos] = ei[e] * DD;       // pre-scaled source offset
    }
}

// ---------------- fused prep: proj (blocks 0..NN-1) + conv_w (rest) --------
__global__ __launch_bounds__(256) void prep_kernel(const float* __restrict__ x,
                                                   const float* __restrict__ Wp,
                                                   const float* __restrict__ bp,
                                                   const float* __restrict__ Wlm,
                                                   const float* __restrict__ Wrm) {
    const int blk = blockIdx.x;
    const int tidx = threadIdx.x;
    if (blk < NN) {
        int n = blk, d = tidx;
        float acc = bp[d];
#pragma unroll
        for (int f = 0; f < FIN; ++f)
            acc += x[n * FIN + f] * Wp[f * DD + d];
        size_t o = (size_t)n * DD + d;
        g_h[o]  = acc;
        g_hh[o] = __float2half(acc);
    } else {
        int idx = blk - NN;
        int j   = idx & (DD - 1);
        int sel = (idx >> 8) & 1;
        int l   = idx >> 9;
        const float* W = (sel ? Wrm : Wlm) + (size_t)l * DD * DD;
        g_wh[(((size_t)l * 2 + sel) * DD + j) * DD + tidx] =
            __float2half(W[tidx * DD + j]);
    }
}

// ---------------- tensor-core GEMM (fp16, 4-stage cp.async, 64x128 blocks) --
__device__ __forceinline__ void mma16816(float* c, const uint32_t* a, const uint32_t* b) {
    asm volatile(
        "mma.sync.aligned.m16n8k16.row.col.f32.f16.f16.f32 "
        "{%0,%1,%2,%3}, {%4,%5,%6,%7}, {%8,%9}, {%0,%1,%2,%3};"
        : "+f"(c[0]), "+f"(c[1]), "+f"(c[2]), "+f"(c[3])
        : "r"(a[0]), "r"(a[1]), "r"(a[2]), "r"(a[3]), "r"(b[0]), "r"(b[1]));
}

__device__ __forceinline__ void cp16(uint32_t dst, const void* src, int srcsz) {
    asm volatile("cp.async.cg.shared.global [%0], [%1], 16, %2;"
                 :: "r"(dst), "l"(src), "r"(srcsz));
}
#define CP_COMMIT() asm volatile("cp.async.commit_group;" ::: "memory")
#define CP_WAIT(n)  asm volatile("cp.async.wait_group %0;" :: "n"(n) : "memory")

__global__ __launch_bounds__(128) void mma_gemm_kernel(int layer) {
    __shared__ __align__(16) __half sA[4][64][16];
    __shared__ __align__(16) __half sB[4][128][16];

    const int tid  = threadIdx.x;
    const int wid  = tid >> 5;
    const int lane = tid & 31;
    const int wm   = wid & 1;
    const int wn   = wid >> 1;
    const int rg   = lane >> 2;
    const int tg   = lane & 3;

    const int mbase   = blockIdx.x * 64;
    const int nhalf   = blockIdx.y & 1;
    const int sel     = blockIdx.y >> 1;
    const int colBase = nhalf * 128;
    const __half* W = g_wh + ((size_t)layer * 2 + sel) * DD * DD;

    const int srow = tid >> 1;
    const int soff = (tid & 1) * 8;
    const int grA  = mbase + srow;
    const size_t gA  = (size_t)grA * DD + soff;
    const size_t gB0 = (size_t)(colBase + srow) * DD + soff;
    const size_t gB1 = (size_t)(colBase + srow + 64) * DD + soff;
    const int predA = (grA < NN) ? 16 : 0;
    const uint32_t uA  = (uint32_t)__cvta_generic_to_shared(&sA[0][0][0])
                       + (uint32_t)(srow * 32 + soff * 2);
    const uint32_t uB0 = (uint32_t)__cvta_generic_to_shared(&sB[0][0][0])
                       + (uint32_t)(srow * 32 + soff * 2);
    const uint32_t uB1 = uB0 + 64u * 32u;

    float acc[2][8][4];
#pragma unroll
    for (int mt = 0; mt < 2; ++mt)
#pragma unroll
        for (int nt = 0; nt < 8; ++nt)
#pragma unroll
            for (int q = 0; q < 4; ++q) acc[mt][nt][q] = 0.f;

#define LOAD_STAGE(kt, buf) do {                                \
        uint32_t boA = (uint32_t)(buf) * 2048u;                 \
        uint32_t boB = (uint32_t)(buf) * 4096u;                 \
        cp16(uA  + boA, g_hh + gA  + (kt) * 16, predA);         \
        cp16(uB0 + boB, W    + gB0 + (kt) * 16, 16);            \
        cp16(uB1 + boB, W    + gB1 + (kt) * 16, 16);            \
    } while (0)

    LOAD_STAGE(0, 0); CP_COMMIT();
    LOAD_STAGE(1, 1); CP_COMMIT();
    LOAD_STAGE(2, 2); CP_COMMIT();

    for (int kt = 0; kt < 16; ++kt) {
        const int buf = kt & 3;
        CP_WAIT(2);
        __syncthreads();
        if (kt + 3 < 16) LOAD_STAGE(kt + 3, (kt + 3) & 3);
        CP_COMMIT();

        uint32_t a[2][4];
#pragma unroll
        for (int mt = 0; mt < 2; ++mt) {
            int r = wm * 32 + mt * 16;
            a[mt][0] = *(const uint32_t*)&sA[buf][r + rg    ][tg * 2    ];
            a[mt][1] = *(const uint32_t*)&sA[buf][r + rg + 8][tg * 2    ];
            a[mt][2] = *(const uint32_t*)&sA[buf][r + rg    ][tg * 2 + 8];
            a[mt][3] = *(const uint32_t*)&sA[buf][r + rg + 8][tg * 2 + 8];
        }
        uint32_t b[8][2];
#pragma unroll
        for (int nt = 0; nt < 8; ++nt) {
            int n = wn * 64 + nt * 8 + rg;
            b[nt][0] = *(const uint32_t*)&sB[buf][n][tg * 2    ];
            b[nt][1] = *(const uint32_t*)&sB[buf][n][tg * 2 + 8];
        }
#pragma unroll
        for (int mt = 0; mt < 2; ++mt)
#pragma unroll
            for (int nt = 0; nt < 8; ++nt)
                mma16816(acc[mt][nt], a[mt], b[nt]);
    }
#undef LOAD_STAGE

#pragma unroll
    for (int mt = 0; mt < 2; ++mt) {
#pragma unroll
        for (int nt = 0; nt < 8; ++nt) {
            int row0 = mbase + wm * 32 + mt * 16 + rg;
            int col  = colBase + wn * 64 + nt * 8 + tg * 2;
            if (sel == 0) {
                if (row0 < NN)
                    *(__half2*)&g_xlh[(size_t)row0 * DD + col] =
                        __floats2half2_rn(acc[mt][nt][0], acc[mt][nt][1]);
                if (row0 + 8 < NN)
                    *(__half2*)&g_xlh[(size_t)(row0 + 8) * DD + col] =
                        __floats2half2_rn(acc[mt][nt][2], acc[mt][nt][3]);
            } else {
                if (row0 < NN)
                    *(float2*)&g_xr[(size_t)row0 * DD + col] =
                        make_float2(acc[mt][nt][0], acc[mt][nt][1]);
                if (row0 + 8 < NN)
                    *(float2*)&g_xr[(size_t)(row0 + 8) * DD + col] =
                        make_float2(acc[mt][nt][2], acc[mt][nt][3]);
            }
        }
    }
}

// ---------------- GATv2: one warp per node, lane = 8 channels ---------------
// Head = 32 channels = 4 lanes -> logit reduce with 2 shfls. One uint4 fp16
// gather per lane per edge. g_csrc holds src*DD (pre-scaled, 32-bit math).
__device__ __forceinline__ void cvt8(float* f, const uint4 u) {
    float2 t;
    t = __half22float2(*(const __half2*)&u.x); f[0] = t.x; f[1] = t.y;
    t = __half22float2(*(const __half2*)&u.y); f[2] = t.x; f[3] = t.y;
    t = __half22float2(*(const __half2*)&u.z); f[4] = t.x; f[5] = t.y;
    t = __half22float2(*(const __half2*)&u.w); f[6] = t.x; f[7] = t.y;
}

__global__ __launch_bounds__(256) void gat_kernel(const float* __restrict__ att_l,
                                                  const float* __restrict__ bconv_l) {
    const int w    = threadIdx.x >> 5;
    const int lane = threadIdx.x & 31;
    const int n    = blockIdx.x * 8 + w;
    const int d    = lane * 8;

    const int r0 = g_rowptr[n];
    const int r1 = g_rowptr[n + 1];

    float xr[8], att[8];
    {
        const float4* p = (const float4*)&g_xr[(size_t)n * DD + d];
        float4 a = p[0], b = p[1];
        xr[0] = a.x; xr[1] = a.y; xr[2] = a.z; xr[3] = a.w;
        xr[4] = b.x; xr[5] = b.y; xr[6] = b.z; xr[7] = b.w;
        const float4* q = (const float4*)&att_l[d];
        float4 c = q[0], e = q[1];
        att[0] = c.x; att[1] = c.y; att[2] = c.z; att[3] = c.w;
        att[4] = e.x; att[5] = e.y; att[6] = e.z; att[7] = e.w;
    }

    float acc[8];
#pragma unroll
    for (int i = 0; i < 8; ++i) acc[i] = 0.f;
    float ssum = 0.f;

    const __half* __restrict__ xlb = g_xlh;

    int k = r0;
    for (; k + 1 < r1; k += 2) {
        int o0 = g_csrc[k];
        int o1 = g_csrc[k + 1];
        uint4 ua = *(const uint4*)(xlb + o0 + d);
        uint4 ub = *(const uint4*)(xlb + o1 + d);
        float fa[8], fb[8];
        cvt8(fa, ua);
        cvt8(fb, ub);

        float pa = 0.f, pb = 0.f;
#pragma unroll
        for (int i = 0; i < 8; ++i) {
            float va = fa[i] + xr[i];
            float vb = fb[i] + xr[i];
            pa += fmaxf(va, SLOPE * va) * att[i];
            pb += fmaxf(vb, SLOPE * vb) * att[i];
        }
        pa += __shfl_xor_sync(0xffffffffu, pa, 1);
        pb += __shfl_xor_sync(0xffffffffu, pb, 1);
        pa += __shfl_xor_sync(0xffffffffu, pa, 2);
        pb += __shfl_xor_sync(0xffffffffu, pb, 2);

        float wa = __expf(pa);
        float wb = __expf(pb);
#pragma unroll
        for (int i = 0; i < 8; ++i)
            acc[i] += wa * fa[i] + wb * fb[i];
        ssum += wa + wb;
    }
    if (k < r1) {
        int o0 = g_csrc[k];
        uint4 ua = *(const uint4*)(xlb + o0 + d);
        float fa[8];
        cvt8(fa, ua);
        float pa = 0.f;
#pragma unroll
        for (int i = 0; i < 8; ++i) {
            float va = fa[i] + xr[i];
            pa += fmaxf(va, SLOPE * va) * att[i];
        }
        pa += __shfl_xor_sync(0xffffffffu, pa, 1);
        pa += __shfl_xor_sync(0xffffffffu, pa, 2);
        float wa = __expf(pa);
#pragma unroll
        for (int i = 0; i < 8; ++i)
            acc[i] += wa * fa[i];
        ssum += wa;
    }

    const float inv = (r1 > r0) ? (1.f / ssum) : 0.f;
    const size_t o = (size_t)n * DD + d;
    float hv[8];
    {
        const float4* ph = (const float4*)&g_h[o];
        float4 a = ph[0], b = ph[1];
        hv[0] = a.x; hv[1] = a.y; hv[2] = a.z; hv[3] = a.w;
        hv[4] = b.x; hv[5] = b.y; hv[6] = b.z; hv[7] = b.w;
        const float4* pb4 = (const float4*)&bconv_l[d];
        float4 c = pb4[0], e = pb4[1];
        float bc[8] = {c.x, c.y, c.z, c.w, e.x, e.y, e.z, e.w};
#pragma unroll
        for (int i = 0; i < 8; ++i)
            hv[i] += acc[i] * inv + bc[i];
    }
    ((float4*)&g_h[o])[0] = make_float4(hv[0], hv[1], hv[2], hv[3]);
    ((float4*)&g_h[o])[1] = make_float4(hv[4], hv[5], hv[6], hv[7]);

    uint4 hu;
    *(__half2*)&hu.x = __floats2half2_rn(hv[0], hv[1]);
    *(__half2*)&hu.y = __floats2half2_rn(hv[2], hv[3]);
    *(__half2*)&hu.z = __floats2half2_rn(hv[4], hv[5]);
    *(__half2*)&hu.w = __floats2half2_rn(hv[6], hv[7]);
    *(uint4*)&g_hh[o] = hu;
}

// ---------------- global mean pool + counts (run-compressed atomics) --------
__global__ void pool_kernel(const int* __restrict__ batch) {
    const int d = threadIdx.x;
    const int per = (NN + gridDim.x - 1) / gridDim.x;
    int n0 = blockIdx.x * per;
    int n1 = n0 + per; if (n1 > NN) n1 = NN;
    if (n0 >= n1) return;
    int cur = batch[n0];
    float accv = 0.f;
    int   cc   = 0;
    for (int n = n0; n < n1; ++n) {
        int b = batch[n];
        if (b != cur) {
            atomicAdd(&g_pool[cur * DD + d], accv);
            if (d == 0) atomicAdd(&g_cnt[cur], (float)cc);
            accv = 0.f; cc = 0;
            cur = b;
        }
        accv += g_h[(size_t)n * DD + d];
        cc   += 1;
    }
    atomicAdd(&g_pool[cur * DD + d], accv);
    if (d == 0) atomicAdd(&g_cnt[cur], (float)cc);
}

// ---------------- prediction head ----------------
__global__ void pred_kernel(const float* __restrict__ Wpred,
                            const float* __restrict__ bpred,
                            float* __restrict__ out) {
    const int g    = threadIdx.x >> 5;
    const int lane = threadIdx.x & 31;
    float s = 0.f;
    for (int d = lane; d < DD; d += 32)
        s += g_pool[g * DD + d] * Wpred[d];
#pragma unroll
    for (int off = 16; off; off >>= 1)
        s += __shfl_xor_sync(0xffffffffu, s, off);
    if (lane == 0)
        out[g] = s / fmaxf(g_cnt[g], 1.0f) + bpred[0];
}

// ---------------- launch (8 kernels; slot 4 = gat_kernel, profiled) ---------
extern "C" void kernel_launch(void* const* d_in, const int* in_sizes, int n_in,
                              void* d_out, int out_size) {
    const float* x     = (const float*)d_in[0];
    const int*   ei    = (const int*)  d_in[1];
    const int*   batch = (const int*)  d_in[2];
    const float* Wp    = (const float*)d_in[3];
    const float* bp    = (const float*)d_in[4];
    const float* Wl    = (const float*)d_in[5];
    const float* Wr    = (const float*)d_in[6];
    const float* att   = (const float*)d_in[7];
    const float* bconv = (const float*)d_in[8];
    const float* Wpred = (const float*)d_in[9];
    const float* bpred = (const float*)d_in[10];
    float* out = (float*)d_out;

    dim3 ggrid((NN + 63) / 64, 4);

    csr_kernel<<<CSR_BLOCKS, 256>>>(ei);                       // 1
    prep_kernel<<<NN + 2 * 2 * DD, 256>>>(x, Wp, bp, Wl, Wr);  // 2
    mma_gemm_kernel<<<ggrid, 128>>>(0);                        // 3
    gat_kernel<<<NN / 8, 256>>>(att, bconv);                   // 4 (profiled)
    mma_gemm_kernel<<<ggrid, 128>>>(1);                        // 5
    gat_kernel<<<NN / 8, 256>>>(att + HH * CC, bconv + DD);    // 6
    pool_kernel<<<64, DD>>>(batch);                            // 7
    pred_kernel<<<1, GG * 32>>>(Wpred, bpred, out);            // 8
}